// round 1
// baseline (speedup 1.0000x reference)
#include <cuda_runtime.h>

#define Bsz 2048
#define Tsz 512
#define Asz 32
#define Hsz 16

__device__ __forceinline__ float sigmoidf_(float x) {
    // 1/(1+e^-x); robust: expf overflow -> inf -> rcp -> 0 (correct limit)
    return __fdividef(1.0f, 1.0f + __expf(-x));
}
__device__ __forceinline__ float tanhf_(float x) {
    float ax = fabsf(x);
    float u  = __expf(-2.0f * ax);
    float r  = __fdividef(1.0f - u, 1.0f + u);
    return (x < 0.0f) ? -r : r;
}

__global__ void __launch_bounds__(64, 7) lstm_fused_kernel(
    const float* __restrict__ xin,      // [B,T,A]
    const float* __restrict__ masks,    // [B,T]
    const float* __restrict__ h0,       // [1,B,H]
    const float* __restrict__ c0,       // [1,B,H]
    const float* __restrict__ w_ih,     // [4H,A]
    const float* __restrict__ w_hh,     // [4H,H]
    const float* __restrict__ b_ih,     // [4H]
    const float* __restrict__ b_hh,     // [4H]
    const float* __restrict__ w_actor,  // [A,H]
    const float* __restrict__ b_actor,  // [A]
    const float* __restrict__ w_critic, // [1,H]
    const float* __restrict__ b_critic, // [1]
    float* __restrict__ actor,          // [B,T,A]
    float* __restrict__ critic,         // [B,T]
    float* __restrict__ hT,             // [B,H]
    float* __restrict__ cT)             // [B,H]
{
    // per-warp staging: [0:32) = x_t, [32:48) = h_{t-1}
    __shared__ __align__(16) float stage[2][48];
    // actor weights, padded rows (20 floats) for conflict-free strided LDS.128
    __shared__ __align__(16) float wact_s[32][20];

    const int tid  = threadIdx.x;
    const int w    = tid >> 5;
    const int lane = tid & 31;
    const int j    = lane & 15;
    const bool hi  = lane >= 16;
    const int b    = blockIdx.x * 2 + w;

    for (int i = tid; i < Asz * Hsz; i += 64) {
        wact_s[i >> 4][i & 15] = w_actor[i];
    }

    // gate row assignment (torch order i,f,g,o):
    //   lane j      (lo): gateA = i_j (row j),     gateB = g_j (row 32+j)
    //   lane 16+j   (hi): gateA = f_j (row 16+j),  gateB = o_j (row 48+j)
    const int rowA = hi ? (16 + j) : j;
    const int rowB = hi ? (48 + j) : (32 + j);

    float wA[48], wB[48];
#pragma unroll
    for (int k = 0; k < 32; k++) {
        wA[k] = w_ih[rowA * 32 + k];
        wB[k] = w_ih[rowB * 32 + k];
    }
#pragma unroll
    for (int k = 0; k < 16; k++) {
        wA[32 + k] = w_hh[rowA * 16 + k];
        wB[32 + k] = w_hh[rowB * 16 + k];
    }
    const float biasA = b_ih[rowA] + b_hh[rowA];
    const float biasB = b_ih[rowB] + b_hh[rowB];
    const float bact  = b_actor[lane];
    const float wc    = hi ? w_critic[j] : 0.0f;
    const float bcr   = b_critic[0];

    float c = hi ? c0[b * Hsz + j] : 0.0f;

    if (hi) stage[w][32 + j] = h0[b * Hsz + j];
    stage[w][lane] = xin[(size_t)b * Tsz * Asz + lane]; // x_0
    __syncthreads();

    const float* xb   = xin + (size_t)b * Tsz * Asz;
    const float* mb   = masks + (size_t)b * Tsz;
    float* actb       = actor + (size_t)b * Tsz * Asz;
    float* crb        = critic + (size_t)b * Tsz;

    float h2 = 0.0f;

    for (int t = 0; t < Tsz; t++) {
        const float m  = mb[t];                                     // L1-resident
        const float xn = (t + 1 < Tsz) ? xb[(t + 1) * Asz + lane]   // prefetch x_{t+1}
                                       : 0.0f;

        float aAx = biasA, aBx = biasB, aAh = 0.0f, aBh = 0.0f;
#pragma unroll
        for (int q = 0; q < 8; q++) {  // x part (32 floats, broadcast LDS.128)
            const float4 v = *reinterpret_cast<const float4*>(&stage[w][q * 4]);
            aAx = fmaf(wA[q * 4 + 0], v.x, aAx); aBx = fmaf(wB[q * 4 + 0], v.x, aBx);
            aAx = fmaf(wA[q * 4 + 1], v.y, aAx); aBx = fmaf(wB[q * 4 + 1], v.y, aBx);
            aAx = fmaf(wA[q * 4 + 2], v.z, aAx); aBx = fmaf(wB[q * 4 + 2], v.z, aBx);
            aAx = fmaf(wA[q * 4 + 3], v.w, aAx); aBx = fmaf(wB[q * 4 + 3], v.w, aBx);
        }
#pragma unroll
        for (int q = 0; q < 4; q++) {  // h part (16 floats)
            const float4 v = *reinterpret_cast<const float4*>(&stage[w][32 + q * 4]);
            aAh = fmaf(wA[32 + q * 4 + 0], v.x, aAh); aBh = fmaf(wB[32 + q * 4 + 0], v.x, aBh);
            aAh = fmaf(wA[32 + q * 4 + 1], v.y, aAh); aBh = fmaf(wB[32 + q * 4 + 1], v.y, aBh);
            aAh = fmaf(wA[32 + q * 4 + 2], v.z, aAh); aBh = fmaf(wB[32 + q * 4 + 2], v.z, aBh);
            aAh = fmaf(wA[32 + q * 4 + 3], v.w, aAh); aBh = fmaf(wB[32 + q * 4 + 3], v.w, aBh);
        }
        // mask folded: gate uses h*m  ->  acc_x + m*acc_h
        const float gA = fmaf(m, aAh, aAx);
        const float gB = fmaf(m, aBh, aBx);

        const float vA = sigmoidf_(gA);                       // lo: i, hi: f
        const float vB = hi ? sigmoidf_(gB) : tanhf_(gB);     // lo: g, hi: o
        const float p  = vA * vB;                             // lo: i*g
        const float ig = __shfl_sync(0xffffffffu, p, j);      // hi lanes fetch i*g

        if (hi) {
            c  = fmaf(vA, c * m, ig);   // c2 = f*(c*m) + i*g
            h2 = vB * tanhf_(c);        // h2 = o*tanh(c2)
        }
        __syncwarp();                    // gate LDS reads done before overwriting stage
        if (hi) stage[w][32 + j] = h2;
        stage[w][lane] = xn;            // stage x_{t+1}
        __syncwarp();

        // ---- actor head: actor[b,t,a=lane] = b_a + sum_k h2[k]*w_actor[a,k]
        float acc = bact;
#pragma unroll
        for (int q = 0; q < 4; q++) {
            const float4 hv = *reinterpret_cast<const float4*>(&stage[w][32 + q * 4]);
            const float4 wv = *reinterpret_cast<const float4*>(&wact_s[lane][q * 4]);
            acc = fmaf(wv.x, hv.x, acc);
            acc = fmaf(wv.y, hv.y, acc);
            acc = fmaf(wv.z, hv.z, acc);
            acc = fmaf(wv.w, hv.w, acc);
        }
        actb[t * Asz + lane] = acc;

        // ---- critic: butterfly reduce h2_j * wc_j over the warp (lo lanes contribute 0)
        float cp = hi ? h2 * wc : 0.0f;
        cp += __shfl_xor_sync(0xffffffffu, cp, 16);
        cp += __shfl_xor_sync(0xffffffffu, cp, 8);
        cp += __shfl_xor_sync(0xffffffffu, cp, 4);
        cp += __shfl_xor_sync(0xffffffffu, cp, 2);
        cp += __shfl_xor_sync(0xffffffffu, cp, 1);
        if (lane == 0) crb[t] = cp + bcr;
    }

    if (hi) {
        hT[b * Hsz + j] = h2;
        cT[b * Hsz + j] = c;
    }
}

extern "C" void kernel_launch(void* const* d_in, const int* in_sizes, int n_in,
                              void* d_out, int out_size) {
    const float* xin      = (const float*)d_in[0];
    const float* masks    = (const float*)d_in[1];
    const float* h0       = (const float*)d_in[2];
    const float* c0       = (const float*)d_in[3];
    const float* w_ih     = (const float*)d_in[4];
    const float* w_hh     = (const float*)d_in[5];
    const float* b_ih     = (const float*)d_in[6];
    const float* b_hh     = (const float*)d_in[7];
    const float* w_actor  = (const float*)d_in[8];
    const float* b_actor  = (const float*)d_in[9];
    const float* w_critic = (const float*)d_in[10];
    const float* b_critic = (const float*)d_in[11];

    float* out    = (float*)d_out;
    float* actor  = out;                                   // B*T*A
    float* critic = actor + (size_t)Bsz * Tsz * Asz;       // B*T
    float* hT     = critic + (size_t)Bsz * Tsz;            // B*H
    float* cT     = hT + (size_t)Bsz * Hsz;                // B*H

    lstm_fused_kernel<<<Bsz / 2, 64>>>(
        xin, masks, h0, c0, w_ih, w_hh, b_ih, b_hh,
        w_actor, b_actor, w_critic, b_critic,
        actor, critic, hT, cT);
}